// round 3
// baseline (speedup 1.0000x reference)
#include <cuda_runtime.h>

#define NN   50000
#define NE   600000
#define FD   128
#define NG   256
#define HIDN 256
#define ODIM 16
#define MAXD 10
#define SCB  512
#define NSCB ((NN + SCB - 1) / SCB)   // 98

typedef unsigned long long u64;

// ---------------- scratch (device globals; no allocs) ----------------
__device__ int   g_degraw[NN];
__device__ int   g_off[NN + 1];
__device__ int   g_cursor[NN];
__device__ int   g_srcv[NE];
__device__ int   g_bcnt[MAXD + 1];
__device__ int   g_boff[MAXD + 2];
__device__ int   g_bcur[MAXD + 1];
__device__ int   g_bnodes[NN];
__device__ int   g_bsum[NSCB];
__device__ float g_X[NN * FD];
__device__ float g_H[NN * FD];
__device__ float g_E[NN * FD];
__device__ float g_P[NN * FD];
__device__ float g_Q[NN * FD];
__device__ float g_Wd[FD * FD];
__device__ float g_G[NG * 2 * FD];

// ---------------- f32x2 helpers ----------------
__device__ __forceinline__ u64 fma2(u64 a, u64 b, u64 c) {
    u64 d; asm("fma.rn.f32x2 %0, %1, %2, %3;" : "=l"(d) : "l"(a), "l"(b), "l"(c)); return d;
}
__device__ __forceinline__ float2 upk(u64 v) {
    float2 f; asm("mov.b64 {%0,%1}, %2;" : "=f"(f.x), "=f"(f.y) : "l"(v)); return f;
}

// ---------------- prep ----------------
__global__ void k_init(const float* __restrict__ Wedge) {
    int i = blockIdx.x * blockDim.x + threadIdx.x;
    if (i < NN) { g_degraw[i] = 0; g_cursor[i] = 0; }
    if (i <= MAXD) { g_bcnt[i] = 0; g_bcur[i] = 0; }
    if (i < FD * FD) g_Wd[i] = Wedge[i] - Wedge[FD * FD + i];
}

__global__ void k_count(const int* __restrict__ col) {
    int e = blockIdx.x * blockDim.x + threadIdx.x;
    if (e < NE) atomicAdd(&g_degraw[col[e]], 1);
}

__global__ void k_bcount() {
    __shared__ int h[MAXD + 1];
    int tid = threadIdx.x;
    if (tid <= MAXD) h[tid] = 0;
    __syncthreads();
    int i = blockIdx.x * blockDim.x + tid;
    if (i < NN) atomicAdd(&h[min(g_degraw[i], MAXD)], 1);
    __syncthreads();
    if (tid <= MAXD && h[tid]) atomicAdd(&g_bcnt[tid], h[tid]);
}

__global__ void k_scan1() {
    __shared__ int sd[SCB];
    int tid = threadIdx.x;
    int i = blockIdx.x * SCB + tid;
    sd[tid] = (i < NN) ? g_degraw[i] : 0;
    __syncthreads();
    for (int off = SCB / 2; off > 0; off >>= 1) {
        if (tid < off) sd[tid] += sd[tid + off];
        __syncthreads();
    }
    if (tid == 0) g_bsum[blockIdx.x] = sd[0];
}

__global__ void k_scan2() {
    int s = 0;
    for (int b = 0; b < NSCB; b++) { int v = g_bsum[b]; g_bsum[b] = s; s += v; }
    g_off[NN] = s;
    int t = 0;
    for (int d = 0; d <= MAXD; d++) { g_boff[d] = t; t += g_bcnt[d]; }
    g_boff[MAXD + 1] = t;
}

__global__ void k_scan3() {
    __shared__ int sd[SCB];
    int tid = threadIdx.x;
    int i = blockIdx.x * SCB + tid;
    int v = (i < NN) ? g_degraw[i] : 0;
    sd[tid] = v;
    __syncthreads();
    for (int off = 1; off < SCB; off <<= 1) {
        int t = 0;
        if (tid >= off) t = sd[tid - off];
        __syncthreads();
        if (tid >= off) sd[tid] += t;
        __syncthreads();
    }
    if (i < NN) g_off[i] = g_bsum[blockIdx.x] + sd[tid] - v;
}

__global__ void k_bfill() {
    __shared__ int h[MAXD + 1];
    __shared__ int sbase[MAXD + 1];
    int tid = threadIdx.x;
    if (tid <= MAXD) h[tid] = 0;
    __syncthreads();
    int i = blockIdx.x * blockDim.x + tid;
    int d = -1;
    if (i < NN) { d = min(g_degraw[i], MAXD); atomicAdd(&h[d], 1); }
    __syncthreads();
    if (tid <= MAXD) {
        sbase[tid] = h[tid] ? atomicAdd(&g_bcur[tid], h[tid]) : 0;
        h[tid] = 0;
    }
    __syncthreads();
    if (i < NN) {
        int p = atomicAdd(&h[d], 1);
        g_bnodes[g_boff[d] + sbase[d] + p] = i;
    }
}

__global__ void k_fillcsr(const int* __restrict__ row, const int* __restrict__ col) {
    int e = blockIdx.x * blockDim.x + threadIdx.x;
    if (e < NE) {
        int c = col[e];
        int p = atomicAdd(&g_cursor[c], 1);
        g_srcv[g_off[c] + p] = row[e];
    }
}

// ---------------- neighbor sum ----------------
__global__ void k_nsum(const float* __restrict__ Xext, int use_internal) {
    const float* __restrict__ X = use_internal ? g_X : Xext;
    int warp = (blockIdx.x * blockDim.x + threadIdx.x) >> 5;
    int lane = threadIdx.x & 31;
    if (warp >= NN) return;
    int beg = g_off[warp], end = g_off[warp + 1];
    float4 acc = make_float4(0.f, 0.f, 0.f, 0.f);
    for (int e = beg; e < end; e++) {
        int s = g_srcv[e];
        float4 v = *(const float4*)(X + (size_t)s * FD + lane * 4);
        acc.x += v.x; acc.y += v.y; acc.z += v.z; acc.w += v.w;
    }
    *(float4*)(g_H + (size_t)warp * FD + lane * 4) = acc;
}

// ---------------- MFConv bucketed dual-GEMM (f32x2, pre-duplicated W) ----------------
__global__ void __launch_bounds__(256) k_mf(
        const float* __restrict__ Xext, int use_internal,
        const float* __restrict__ Wlin, const float* __restrict__ blin,
        const float* __restrict__ Wroot, float* __restrict__ emb) {
    const float* __restrict__ Xin = use_internal ? g_X : Xext;
    int d = blockIdx.y;
    int bstart = g_boff[d];
    int bcnt = g_boff[d + 1] - bstart;
    int base = blockIdx.x * 64;
    if (base >= bcnt) return;
    int nv = min(64, bcnt - base);

    __shared__ int   s_node[64];
    __shared__ float sWl[16][256];   // duplicated: [kk][2o]=[kk][2o+1]=W[k0+kk][o]
    __shared__ float sWr[16][256];
    __shared__ float sAh[16][64];
    __shared__ float sAx[16][64];

    int tid = threadIdx.x;
    if (tid < 64) s_node[tid] = (tid < nv) ? g_bnodes[bstart + base + tid] : -1;
    __syncthreads();

    const float* Wl = Wlin + (size_t)d * FD * FD;
    const float* Wr = Wroot + (size_t)d * FD * FD;

    u64 acc[4][4];
#pragma unroll
    for (int a = 0; a < 4; a++)
#pragma unroll
        for (int b = 0; b < 4; b++) acc[a][b] = 0ull;

    int o0 = (tid & 31) * 4;
    int n0 = (tid >> 5) * 8;

    for (int k0 = 0; k0 < FD; k0 += 16) {
        __syncthreads();
        {   // stage W duplicated: chunk = 16x128 source floats per matrix
            const float4* Wl4 = (const float4*)(Wl + (size_t)k0 * FD);
            const float4* Wr4 = (const float4*)(Wr + (size_t)k0 * FD);
            float4* dWl = (float4*)&sWl[0][0];
            float4* dWr = (float4*)&sWr[0][0];
#pragma unroll
            for (int i = 0; i < 2; i++) {
                int j = tid + i * 256;          // source float4 index (512 total)
                float4 w = Wl4[j];
                dWl[2 * j]     = make_float4(w.x, w.x, w.y, w.y);
                dWl[2 * j + 1] = make_float4(w.z, w.z, w.w, w.w);
                float4 v = Wr4[j];
                dWr[2 * j]     = make_float4(v.x, v.x, v.y, v.y);
                dWr[2 * j + 1] = make_float4(v.z, v.z, v.w, v.w);
            }
        }
        {   // stage A (transposed to [k][n])
            int n = tid >> 2;
            int kq = tid & 3;
            int node = s_node[n];
            float4 vh = make_float4(0.f, 0.f, 0.f, 0.f);
            float4 vx = vh;
            if (node >= 0) {
                vh = *(const float4*)(g_H + (size_t)node * FD + k0 + kq * 4);
                vx = *(const float4*)(Xin + (size_t)node * FD + k0 + kq * 4);
            }
            sAh[kq * 4 + 0][n] = vh.x; sAh[kq * 4 + 1][n] = vh.y;
            sAh[kq * 4 + 2][n] = vh.z; sAh[kq * 4 + 3][n] = vh.w;
            sAx[kq * 4 + 0][n] = vx.x; sAx[kq * 4 + 1][n] = vx.y;
            sAx[kq * 4 + 2][n] = vx.z; sAx[kq * 4 + 3][n] = vx.w;
        }
        __syncthreads();
#pragma unroll
        for (int kk = 0; kk < 16; kk++) {
            ulonglong2 wlA = *(const ulonglong2*)&sWl[kk][2 * o0];
            ulonglong2 wlB = *(const ulonglong2*)&sWl[kk][2 * o0 + 4];
            ulonglong2 wrA = *(const ulonglong2*)&sWr[kk][2 * o0];
            ulonglong2 wrB = *(const ulonglong2*)&sWr[kk][2 * o0 + 4];
            u64 wl2[4] = {wlA.x, wlA.y, wlB.x, wlB.y};
            u64 wr2[4] = {wrA.x, wrA.y, wrB.x, wrB.y};
            ulonglong2 ahA = *(const ulonglong2*)&sAh[kk][n0];
            ulonglong2 ahB = *(const ulonglong2*)&sAh[kk][n0 + 4];
            ulonglong2 axA = *(const ulonglong2*)&sAx[kk][n0];
            ulonglong2 axB = *(const ulonglong2*)&sAx[kk][n0 + 4];
            u64 ah2[4] = {ahA.x, ahA.y, ahB.x, ahB.y};
            u64 ax2[4] = {axA.x, axA.y, axB.x, axB.y};
#pragma unroll
            for (int a = 0; a < 4; a++) {
                u64 ahv = ah2[a], axv = ax2[a];
#pragma unroll
                for (int b = 0; b < 4; b++) {
                    acc[a][b] = fma2(ahv, wl2[b], acc[a][b]);
                    acc[a][b] = fma2(axv, wr2[b], acc[a][b]);
                }
            }
        }
    }
    float4 bl = *(const float4*)(blin + (size_t)d * FD + o0);
    float bv[4] = {bl.x, bl.y, bl.z, bl.w};
#pragma unroll
    for (int a = 0; a < 4; a++) {
        float2 c0 = upk(acc[a][0]), c1 = upk(acc[a][1]);
        float2 c2 = upk(acc[a][2]), c3 = upk(acc[a][3]);
#pragma unroll
        for (int half = 0; half < 2; half++) {
            int node = s_node[n0 + 2 * a + half];
            if (node < 0) continue;
            float4 v;
            v.x = (half ? c0.y : c0.x) + bv[0];
            v.y = (half ? c1.y : c1.x) + bv[1];
            v.z = (half ? c2.y : c2.x) + bv[2];
            v.w = (half ? c3.y : c3.x) + bv[3];
            if (emb) *(float4*)(emb + (size_t)node * FD + o0) = v;
            float4 r;
            r.x = fmaxf(v.x, 0.f); r.y = fmaxf(v.y, 0.f);
            r.z = fmaxf(v.z, 0.f); r.w = fmaxf(v.w, 0.f);
            *(float4*)(g_X + (size_t)node * FD + o0) = r;
        }
    }
}

// ---------------- EdgeConv projections (f32x2, pre-duplicated W) ----------------
__global__ void __launch_bounds__(256) k_pq(
        const float* __restrict__ Eext, int use_internal,
        const float* __restrict__ Wedge) {
    const float* __restrict__ Ein = use_internal ? g_E : Eext;
    const float* __restrict__ Wb = Wedge + FD * FD;
    int base = blockIdx.x * 64;

    __shared__ float sWd[16][256];
    __shared__ float sWb[16][256];
    __shared__ float sAe[16][64];

    int tid = threadIdx.x;
    u64 accP[4][4], accQ[4][4];
#pragma unroll
    for (int a = 0; a < 4; a++)
#pragma unroll
        for (int b = 0; b < 4; b++) { accP[a][b] = 0ull; accQ[a][b] = 0ull; }

    int o0 = (tid & 31) * 4;
    int n0 = (tid >> 5) * 8;

    for (int k0 = 0; k0 < FD; k0 += 16) {
        __syncthreads();
        {
            const float4* Wd4 = (const float4*)(g_Wd + (size_t)k0 * FD);
            const float4* Wb4 = (const float4*)(Wb + (size_t)k0 * FD);
            float4* dWd = (float4*)&sWd[0][0];
            float4* dWb = (float4*)&sWb[0][0];
#pragma unroll
            for (int i = 0; i < 2; i++) {
                int j = tid + i * 256;
                float4 w = Wd4[j];
                dWd[2 * j]     = make_float4(w.x, w.x, w.y, w.y);
                dWd[2 * j + 1] = make_float4(w.z, w.z, w.w, w.w);
                float4 v = Wb4[j];
                dWb[2 * j]     = make_float4(v.x, v.x, v.y, v.y);
                dWb[2 * j + 1] = make_float4(v.z, v.z, v.w, v.w);
            }
        }
        {
            int n = tid >> 2;
            int kq = tid & 3;
            int node = base + n;
            float4 v = make_float4(0.f, 0.f, 0.f, 0.f);
            if (node < NN)
                v = *(const float4*)(Ein + (size_t)node * FD + k0 + kq * 4);
            sAe[kq * 4 + 0][n] = v.x; sAe[kq * 4 + 1][n] = v.y;
            sAe[kq * 4 + 2][n] = v.z; sAe[kq * 4 + 3][n] = v.w;
        }
        __syncthreads();
#pragma unroll
        for (int kk = 0; kk < 16; kk++) {
            ulonglong2 wdA = *(const ulonglong2*)&sWd[kk][2 * o0];
            ulonglong2 wdB = *(const ulonglong2*)&sWd[kk][2 * o0 + 4];
            ulonglong2 wbA = *(const ulonglong2*)&sWb[kk][2 * o0];
            ulonglong2 wbB = *(const ulonglong2*)&sWb[kk][2 * o0 + 4];
            u64 wd2[4] = {wdA.x, wdA.y, wdB.x, wdB.y};
            u64 wb2[4] = {wbA.x, wbA.y, wbB.x, wbB.y};
            ulonglong2 aeA = *(const ulonglong2*)&sAe[kk][n0];
            ulonglong2 aeB = *(const ulonglong2*)&sAe[kk][n0 + 4];
            u64 ae2[4] = {aeA.x, aeA.y, aeB.x, aeB.y};
#pragma unroll
            for (int a = 0; a < 4; a++) {
                u64 av = ae2[a];
#pragma unroll
                for (int b = 0; b < 4; b++) {
                    accP[a][b] = fma2(av, wd2[b], accP[a][b]);
                    accQ[a][b] = fma2(av, wb2[b], accQ[a][b]);
                }
            }
        }
    }
#pragma unroll
    for (int a = 0; a < 4; a++) {
        float2 p0 = upk(accP[a][0]), p1 = upk(accP[a][1]);
        float2 p2 = upk(accP[a][2]), p3 = upk(accP[a][3]);
        float2 q0 = upk(accQ[a][0]), q1 = upk(accQ[a][1]);
        float2 q2 = upk(accQ[a][2]), q3 = upk(accQ[a][3]);
#pragma unroll
        for (int half = 0; half < 2; half++) {
            int node = base + n0 + 2 * a + half;
            if (node >= NN) continue;
            float4 p, q;
            p.x = half ? p0.y : p0.x; p.y = half ? p1.y : p1.x;
            p.z = half ? p2.y : p2.x; p.w = half ? p3.y : p3.x;
            q.x = half ? q0.y : q0.x; q.y = half ? q1.y : q1.x;
            q.z = half ? q2.y : q2.x; q.w = half ? q3.y : q3.x;
            *(float4*)(g_P + (size_t)node * FD + o0) = p;
            *(float4*)(g_Q + (size_t)node * FD + o0) = q;
        }
    }
}

// ---------------- Edge max aggregation ----------------
__global__ void k_edgemax(const float* __restrict__ bedge, float* __restrict__ emb) {
    int warp = (blockIdx.x * blockDim.x + threadIdx.x) >> 5;
    int lane = threadIdx.x & 31;
    if (warp >= NN) return;
    int beg = g_off[warp], end = g_off[warp + 1];
    float4 m = make_float4(-3.402823466e38f, -3.402823466e38f,
                           -3.402823466e38f, -3.402823466e38f);
    for (int e = beg; e < end; e++) {
        int s = g_srcv[e];
        float4 q = *(const float4*)(g_Q + (size_t)s * FD + lane * 4);
        m.x = fmaxf(m.x, q.x); m.y = fmaxf(m.y, q.y);
        m.z = fmaxf(m.z, q.z); m.w = fmaxf(m.w, q.w);
    }
    float4 val;
    if (end > beg) {
        float4 p = *(const float4*)(g_P + (size_t)warp * FD + lane * 4);
        float4 b = *(const float4*)(bedge + lane * 4);
        val.x = p.x + b.x + m.x; val.y = p.y + b.y + m.y;
        val.z = p.z + b.z + m.z; val.w = p.w + b.w + m.w;
    } else {
        val = make_float4(0.f, 0.f, 0.f, 0.f);
    }
    if (emb) *(float4*)(emb + (size_t)warp * FD + lane * 4) = val;
    float4 r;
    r.x = fmaxf(val.x, 0.f); r.y = fmaxf(val.y, 0.f);
    r.z = fmaxf(val.z, 0.f); r.w = fmaxf(val.w, 0.f);
    *(float4*)(g_E + (size_t)warp * FD + lane * 4) = r;
}

// ---------------- graph pooling ----------------
__device__ __forceinline__ int lb_batch(const int* __restrict__ b, int val) {
    int lo = 0, hi = NN;
    while (lo < hi) {
        int mid = (lo + hi) >> 1;
        if (b[mid] < val) lo = mid + 1; else hi = mid;
    }
    return lo;
}

__global__ void k_pool(const int* __restrict__ batch) {
    int g = blockIdx.x;
    int f = threadIdx.x;
    __shared__ int s_lo, s_hi;
    if (f == 0) { s_lo = lb_batch(batch, g); s_hi = lb_batch(batch, g + 1); }
    __syncthreads();
    int lo = s_lo, hi = s_hi;
    float acc = 0.f;
    if (f < FD) {
#pragma unroll 4
        for (int i = lo; i < hi; i++) acc += g_H[(size_t)i * FD + f];
    } else {
        int ff = f - FD;
#pragma unroll 4
        for (int i = lo; i < hi; i++)
            acc += (float)g_degraw[i] * g_E[(size_t)i * FD + ff];
    }
    g_G[g * 2 * FD + f] = acc;
}

// ---------------- readout MLP ----------------
__global__ void k_mlp(const float* __restrict__ W0, const float* __restrict__ b0,
                      const float* __restrict__ W1, const float* __restrict__ b1,
                      float* __restrict__ out) {
    int g = blockIdx.x;
    int j = threadIdx.x;
    __shared__ float sg[2 * FD];
    __shared__ float sh[HIDN];
    sg[j] = g_G[g * 2 * FD + j];
    __syncthreads();
    float a = b0[j];
#pragma unroll 4
    for (int k = 0; k < 2 * FD; k++) a = fmaf(sg[k], W0[k * HIDN + j], a);
    sh[j] = fmaxf(a, 0.f);
    __syncthreads();
    if (j < ODIM) {
        float o = b1[j];
#pragma unroll 4
        for (int k = 0; k < HIDN; k++) o = fmaf(sh[k], W1[k * ODIM + j], o);
        out[g * ODIM + j] = fmaxf(o, 0.f);
    }
}

// ---------------- zero fill for emb_edge rows >= NN ----------------
__global__ void k_zerotail(float* __restrict__ p, long long n4) {
    long long i = (long long)blockIdx.x * blockDim.x + threadIdx.x;
    if (i < n4) ((float4*)p)[i] = make_float4(0.f, 0.f, 0.f, 0.f);
}

// ---------------- launch (fork/join multi-stream) ----------------
extern "C" void kernel_launch(void* const* d_in, const int* in_sizes, int n_in,
                              void* d_out, int out_size) {
    const float* x     = (const float*)d_in[0];
    const float* ea    = (const float*)d_in[1];
    const int*   ei    = (const int*)d_in[2];
    const int*   batch = (const int*)d_in[3];
    const float* Wlin  = (const float*)d_in[4];
    const float* blin  = (const float*)d_in[5];
    const float* Wroot = (const float*)d_in[6];
    const float* Wedge = (const float*)d_in[7];
    const float* bedge = (const float*)d_in[8];
    const float* W0    = (const float*)d_in[9];
    const float* b0    = (const float*)d_in[10];
    const float* W1    = (const float*)d_in[11];
    const float* b1    = (const float*)d_in[12];

    float* out      = (float*)d_out;
    float* emb_node = out + NG * ODIM;
    float* emb_edge = emb_node + (size_t)NN * FD;

    const int* row = ei;
    const int* col = ei + NE;

    static cudaStream_t sB = nullptr, sC = nullptr;
    static cudaEvent_t evStart, evInit, evCSR, evE2, evCdone;
    if (!sB) {
        cudaStreamCreateWithFlags(&sB, cudaStreamNonBlocking);
        cudaStreamCreateWithFlags(&sC, cudaStreamNonBlocking);
        cudaEventCreateWithFlags(&evStart, cudaEventDisableTiming);
        cudaEventCreateWithFlags(&evInit,  cudaEventDisableTiming);
        cudaEventCreateWithFlags(&evCSR,   cudaEventDisableTiming);
        cudaEventCreateWithFlags(&evE2,    cudaEventDisableTiming);
        cudaEventCreateWithFlags(&evCdone, cudaEventDisableTiming);
    }

    dim3 b256(256);
    int gN = (NN + 255) / 256;
    int gE = (NE + 255) / 256;
    int gW = NN / 8;
    dim3 gMF((NN + 63) / 64, MAXD + 1);
    int gPQ = (NN + 63) / 64;

    // ---- fork C: zero tail of emb_edge (no dependencies) ----
    cudaEventRecord(evStart, 0);
    cudaStreamWaitEvent(sC, evStart, 0);
    long long n4 = (long long)(NE - NN) * FD / 4;
    k_zerotail<<<(unsigned)((n4 + 255) / 256), b256, 0, sC>>>(
        emb_edge + (size_t)NN * FD, n4);
    cudaEventRecord(evCdone, sC);

    // ---- main stream: init, then fork B for edge path ----
    k_init<<<gN, b256>>>(Wedge);
    cudaEventRecord(evInit, 0);
    cudaStreamWaitEvent(sB, evInit, 0);
    k_pq<<<gPQ, b256, 0, sB>>>(ea, 0, Wedge);      // pq iter 1 (needs only g_Wd)

    // CSR + bucket prep on main stream
    k_count<<<gE, b256>>>(col);
    k_bcount<<<gN, b256>>>();
    k_scan1<<<NSCB, SCB>>>();
    k_scan2<<<1, 1>>>();
    k_scan3<<<NSCB, SCB>>>();
    k_bfill<<<gN, b256>>>();
    k_fillcsr<<<gE, b256>>>(row, col);
    cudaEventRecord(evCSR, 0);

    // ---- stream B: rest of edge path ----
    cudaStreamWaitEvent(sB, evCSR, 0);
    k_edgemax<<<gW, b256, 0, sB>>>(bedge, nullptr);
    k_pq<<<gPQ, b256, 0, sB>>>(nullptr, 1, Wedge);
    k_edgemax<<<gW, b256, 0, sB>>>(bedge, emb_edge);
    cudaEventRecord(evE2, sB);

    // ---- main stream: node path ----
    k_nsum<<<gW, b256>>>(x, 0);
    k_mf<<<gMF, b256>>>(x, 0, Wlin, blin, Wroot, nullptr);
    k_nsum<<<gW, b256>>>(nullptr, 1);
    k_mf<<<gMF, b256>>>(nullptr, 1, Wlin, blin, Wroot, emb_node);
    k_nsum<<<gW, b256>>>(nullptr, 1);

    // ---- join + readout ----
    cudaStreamWaitEvent(0, evE2, 0);
    k_pool<<<NG, b256>>>(batch);
    k_mlp<<<NG, b256>>>(W0, b0, W1, b1, out);
    cudaStreamWaitEvent(0, evCdone, 0);
}

// round 4
// speedup vs baseline: 1.4725x; 1.4725x over previous
#include <cuda_runtime.h>

#define NN   50000
#define NE   600000
#define FD   128
#define NG   256
#define HIDN 256
#define ODIM 16
#define MAXD 10
#define SCB  512
#define NSCB ((NN + SCB - 1) / SCB)   // 98

typedef unsigned long long u64;

// ---------------- scratch (device globals; no allocs) ----------------
__device__ int   g_degraw[NN];
__device__ int   g_off[NN + 1];
__device__ int   g_cursor[NN];
__device__ int   g_srcv[NE];
__device__ int   g_bcnt[MAXD + 1];
__device__ int   g_boff[MAXD + 2];
__device__ int   g_bcur[MAXD + 1];
__device__ int   g_bnodes[NN];
__device__ int   g_bsum[NSCB];
__device__ float g_X[NN * FD];
__device__ float g_H[NN * FD];
__device__ float g_E[NN * FD];
__device__ float g_P[NN * FD];
__device__ float g_Q[NN * FD];
__device__ float g_Wd[FD * FD];
__device__ float g_G[NG * 2 * FD];

// ---------------- f32x2 helpers ----------------
__device__ __forceinline__ u64 pk2(float a, float b) {
    u64 r; asm("mov.b64 %0, {%1,%2};" : "=l"(r) : "f"(a), "f"(b)); return r;
}
__device__ __forceinline__ u64 fma2(u64 a, u64 b, u64 c) {
    u64 d; asm("fma.rn.f32x2 %0, %1, %2, %3;" : "=l"(d) : "l"(a), "l"(b), "l"(c)); return d;
}
__device__ __forceinline__ float2 upk(u64 v) {
    float2 f; asm("mov.b64 {%0,%1}, %2;" : "=f"(f.x), "=f"(f.y) : "l"(v)); return f;
}

// ---------------- prep ----------------
__global__ void k_init(const float* __restrict__ Wedge) {
    int i = blockIdx.x * blockDim.x + threadIdx.x;
    if (i < NN) { g_degraw[i] = 0; g_cursor[i] = 0; }
    if (i <= MAXD) { g_bcnt[i] = 0; g_bcur[i] = 0; }
    if (i < FD * FD) g_Wd[i] = Wedge[i] - Wedge[FD * FD + i];
}

__global__ void k_count(const int* __restrict__ col) {
    int e = blockIdx.x * blockDim.x + threadIdx.x;
    if (e < NE) atomicAdd(&g_degraw[col[e]], 1);
}

__global__ void k_bcount() {
    __shared__ int h[MAXD + 1];
    int tid = threadIdx.x;
    if (tid <= MAXD) h[tid] = 0;
    __syncthreads();
    int i = blockIdx.x * blockDim.x + tid;
    if (i < NN) atomicAdd(&h[min(g_degraw[i], MAXD)], 1);
    __syncthreads();
    if (tid <= MAXD && h[tid]) atomicAdd(&g_bcnt[tid], h[tid]);
}

__global__ void k_scan1() {
    __shared__ int sd[SCB];
    int tid = threadIdx.x;
    int i = blockIdx.x * SCB + tid;
    sd[tid] = (i < NN) ? g_degraw[i] : 0;
    __syncthreads();
    for (int off = SCB / 2; off > 0; off >>= 1) {
        if (tid < off) sd[tid] += sd[tid + off];
        __syncthreads();
    }
    if (tid == 0) g_bsum[blockIdx.x] = sd[0];
}

__global__ void k_scan2() {
    int s = 0;
    for (int b = 0; b < NSCB; b++) { int v = g_bsum[b]; g_bsum[b] = s; s += v; }
    g_off[NN] = s;
    int t = 0;
    for (int d = 0; d <= MAXD; d++) { g_boff[d] = t; t += g_bcnt[d]; }
    g_boff[MAXD + 1] = t;
}

__global__ void k_scan3() {
    __shared__ int sd[SCB];
    int tid = threadIdx.x;
    int i = blockIdx.x * SCB + tid;
    int v = (i < NN) ? g_degraw[i] : 0;
    sd[tid] = v;
    __syncthreads();
    for (int off = 1; off < SCB; off <<= 1) {
        int t = 0;
        if (tid >= off) t = sd[tid - off];
        __syncthreads();
        if (tid >= off) sd[tid] += t;
        __syncthreads();
    }
    if (i < NN) g_off[i] = g_bsum[blockIdx.x] + sd[tid] - v;
}

__global__ void k_bfill() {
    __shared__ int h[MAXD + 1];
    __shared__ int sbase[MAXD + 1];
    int tid = threadIdx.x;
    if (tid <= MAXD) h[tid] = 0;
    __syncthreads();
    int i = blockIdx.x * blockDim.x + tid;
    int d = -1;
    if (i < NN) { d = min(g_degraw[i], MAXD); atomicAdd(&h[d], 1); }
    __syncthreads();
    if (tid <= MAXD) {
        sbase[tid] = h[tid] ? atomicAdd(&g_bcur[tid], h[tid]) : 0;
        h[tid] = 0;
    }
    __syncthreads();
    if (i < NN) {
        int p = atomicAdd(&h[d], 1);
        g_bnodes[g_boff[d] + sbase[d] + p] = i;
    }
}

__global__ void k_fillcsr(const int* __restrict__ row, const int* __restrict__ col) {
    int e = blockIdx.x * blockDim.x + threadIdx.x;
    if (e < NE) {
        int c = col[e];
        int p = atomicAdd(&g_cursor[c], 1);
        g_srcv[g_off[c] + p] = row[e];
    }
}

// ---------------- neighbor sum ----------------
__global__ void k_nsum(const float* __restrict__ Xext, int use_internal) {
    const float* __restrict__ X = use_internal ? g_X : Xext;
    int warp = (blockIdx.x * blockDim.x + threadIdx.x) >> 5;
    int lane = threadIdx.x & 31;
    if (warp >= NN) return;
    int beg = g_off[warp], end = g_off[warp + 1];
    float4 acc = make_float4(0.f, 0.f, 0.f, 0.f);
    for (int e = beg; e < end; e++) {
        int s = g_srcv[e];
        float4 v = *(const float4*)(X + (size_t)s * FD + lane * 4);
        acc.x += v.x; acc.y += v.y; acc.z += v.z; acc.w += v.w;
    }
    *(float4*)(g_H + (size_t)warp * FD + lane * 4) = acc;
}

// ---------------- MFConv bucketed dual-GEMM (f32x2; round-2 proven version) ----------------
__global__ void __launch_bounds__(256) k_mf(
        const float* __restrict__ Xext, int use_internal,
        const float* __restrict__ Wlin, const float* __restrict__ blin,
        const float* __restrict__ Wroot, float* __restrict__ emb) {
    const float* __restrict__ Xin = use_internal ? g_X : Xext;
    int d = blockIdx.y;
    int bstart = g_boff[d];
    int bcnt = g_boff[d + 1] - bstart;
    int base = blockIdx.x * 64;
    if (base >= bcnt) return;
    int nv = min(64, bcnt - base);

    __shared__ int   s_node[64];
    __shared__ float sWl[16][128];
    __shared__ float sWr[16][128];
    __shared__ float sAh[16][64];
    __shared__ float sAx[16][64];

    int tid = threadIdx.x;
    if (tid < 64) s_node[tid] = (tid < nv) ? g_bnodes[bstart + base + tid] : -1;
    __syncthreads();

    const float* Wl = Wlin + (size_t)d * FD * FD;
    const float* Wr = Wroot + (size_t)d * FD * FD;

    u64 acc[4][4];
#pragma unroll
    for (int a = 0; a < 4; a++)
#pragma unroll
        for (int b = 0; b < 4; b++) acc[a][b] = 0ull;

    int o0 = (tid & 31) * 4;
    int n0 = (tid >> 5) * 8;

    for (int k0 = 0; k0 < FD; k0 += 16) {
        __syncthreads();
        {
            const float4* Wl4 = (const float4*)(Wl + (size_t)k0 * FD);
            const float4* Wr4 = (const float4*)(Wr + (size_t)k0 * FD);
            float4* sWl4 = (float4*)&sWl[0][0];
            float4* sWr4 = (float4*)&sWr[0][0];
            sWl4[tid] = Wl4[tid]; sWl4[tid + 256] = Wl4[tid + 256];
            sWr4[tid] = Wr4[tid]; sWr4[tid + 256] = Wr4[tid + 256];
        }
        {
            int n = tid >> 2;
            int kq = tid & 3;
            int node = s_node[n];
            float4 vh = make_float4(0.f, 0.f, 0.f, 0.f);
            float4 vx = vh;
            if (node >= 0) {
                vh = *(const float4*)(g_H + (size_t)node * FD + k0 + kq * 4);
                vx = *(const float4*)(Xin + (size_t)node * FD + k0 + kq * 4);
            }
            sAh[kq * 4 + 0][n] = vh.x; sAh[kq * 4 + 1][n] = vh.y;
            sAh[kq * 4 + 2][n] = vh.z; sAh[kq * 4 + 3][n] = vh.w;
            sAx[kq * 4 + 0][n] = vx.x; sAx[kq * 4 + 1][n] = vx.y;
            sAx[kq * 4 + 2][n] = vx.z; sAx[kq * 4 + 3][n] = vx.w;
        }
        __syncthreads();
#pragma unroll
        for (int kk = 0; kk < 16; kk++) {
            float4 wl = *(const float4*)&sWl[kk][o0];
            float4 wr = *(const float4*)&sWr[kk][o0];
            u64 wl2[4] = {pk2(wl.x, wl.x), pk2(wl.y, wl.y), pk2(wl.z, wl.z), pk2(wl.w, wl.w)};
            u64 wr2[4] = {pk2(wr.x, wr.x), pk2(wr.y, wr.y), pk2(wr.z, wr.z), pk2(wr.w, wr.w)};
            const u64* ah2 = (const u64*)&sAh[kk][n0];
            const u64* ax2 = (const u64*)&sAx[kk][n0];
#pragma unroll
            for (int a = 0; a < 4; a++) {
                u64 ahv = ah2[a], axv = ax2[a];
#pragma unroll
                for (int b = 0; b < 4; b++) {
                    acc[a][b] = fma2(ahv, wl2[b], acc[a][b]);
                    acc[a][b] = fma2(axv, wr2[b], acc[a][b]);
                }
            }
        }
    }
    float4 bl = *(const float4*)(blin + (size_t)d * FD + o0);
    float bv[4] = {bl.x, bl.y, bl.z, bl.w};
#pragma unroll
    for (int a = 0; a < 4; a++) {
        float2 c0 = upk(acc[a][0]), c1 = upk(acc[a][1]);
        float2 c2 = upk(acc[a][2]), c3 = upk(acc[a][3]);
#pragma unroll
        for (int half = 0; half < 2; half++) {
            int node = s_node[n0 + 2 * a + half];
            if (node < 0) continue;
            float4 v;
            v.x = (half ? c0.y : c0.x) + bv[0];
            v.y = (half ? c1.y : c1.x) + bv[1];
            v.z = (half ? c2.y : c2.x) + bv[2];
            v.w = (half ? c3.y : c3.x) + bv[3];
            if (emb) *(float4*)(emb + (size_t)node * FD + o0) = v;
            float4 r;
            r.x = fmaxf(v.x, 0.f); r.y = fmaxf(v.y, 0.f);
            r.z = fmaxf(v.z, 0.f); r.w = fmaxf(v.w, 0.f);
            *(float4*)(g_X + (size_t)node * FD + o0) = r;
        }
    }
}

// ---------------- EdgeConv projections (f32x2; round-2 proven version) ----------------
__global__ void __launch_bounds__(256) k_pq(
        const float* __restrict__ Eext, int use_internal,
        const float* __restrict__ Wedge) {
    const float* __restrict__ Ein = use_internal ? g_E : Eext;
    const float* __restrict__ Wb = Wedge + FD * FD;
    int base = blockIdx.x * 64;

    __shared__ float sWd[16][128];
    __shared__ float sWb[16][128];
    __shared__ float sAe[16][64];

    int tid = threadIdx.x;
    u64 accP[4][4], accQ[4][4];
#pragma unroll
    for (int a = 0; a < 4; a++)
#pragma unroll
        for (int b = 0; b < 4; b++) { accP[a][b] = 0ull; accQ[a][b] = 0ull; }

    int o0 = (tid & 31) * 4;
    int n0 = (tid >> 5) * 8;

    for (int k0 = 0; k0 < FD; k0 += 16) {
        __syncthreads();
        {
            const float4* Wd4 = (const float4*)(g_Wd + (size_t)k0 * FD);
            const float4* Wb4 = (const float4*)(Wb + (size_t)k0 * FD);
            float4* sWd4 = (float4*)&sWd[0][0];
            float4* sWb4 = (float4*)&sWb[0][0];
            sWd4[tid] = Wd4[tid]; sWd4[tid + 256] = Wd4[tid + 256];
            sWb4[tid] = Wb4[tid]; sWb4[tid + 256] = Wb4[tid + 256];
        }
        {
            int n = tid >> 2;
            int kq = tid & 3;
            int node = base + n;
            float4 v = make_float4(0.f, 0.f, 0.f, 0.f);
            if (node < NN)
                v = *(const float4*)(Ein + (size_t)node * FD + k0 + kq * 4);
            sAe[kq * 4 + 0][n] = v.x; sAe[kq * 4 + 1][n] = v.y;
            sAe[kq * 4 + 2][n] = v.z; sAe[kq * 4 + 3][n] = v.w;
        }
        __syncthreads();
#pragma unroll
        for (int kk = 0; kk < 16; kk++) {
            float4 wd = *(const float4*)&sWd[kk][o0];
            float4 wb = *(const float4*)&sWb[kk][o0];
            u64 wd2[4] = {pk2(wd.x, wd.x), pk2(wd.y, wd.y), pk2(wd.z, wd.z), pk2(wd.w, wd.w)};
            u64 wb2[4] = {pk2(wb.x, wb.x), pk2(wb.y, wb.y), pk2(wb.z, wb.z), pk2(wb.w, wb.w)};
            const u64* ae2 = (const u64*)&sAe[kk][n0];
#pragma unroll
            for (int a = 0; a < 4; a++) {
                u64 av = ae2[a];
#pragma unroll
                for (int b = 0; b < 4; b++) {
                    accP[a][b] = fma2(av, wd2[b], accP[a][b]);
                    accQ[a][b] = fma2(av, wb2[b], accQ[a][b]);
                }
            }
        }
    }
#pragma unroll
    for (int a = 0; a < 4; a++) {
        float2 p0 = upk(accP[a][0]), p1 = upk(accP[a][1]);
        float2 p2 = upk(accP[a][2]), p3 = upk(accP[a][3]);
        float2 q0 = upk(accQ[a][0]), q1 = upk(accQ[a][1]);
        float2 q2 = upk(accQ[a][2]), q3 = upk(accQ[a][3]);
#pragma unroll
        for (int half = 0; half < 2; half++) {
            int node = base + n0 + 2 * a + half;
            if (node >= NN) continue;
            float4 p, q;
            p.x = half ? p0.y : p0.x; p.y = half ? p1.y : p1.x;
            p.z = half ? p2.y : p2.x; p.w = half ? p3.y : p3.x;
            q.x = half ? q0.y : q0.x; q.y = half ? q1.y : q1.x;
            q.z = half ? q2.y : q2.x; q.w = half ? q3.y : q3.x;
            *(float4*)(g_P + (size_t)node * FD + o0) = p;
            *(float4*)(g_Q + (size_t)node * FD + o0) = q;
        }
    }
}

// ---------------- Edge max aggregation ----------------
__global__ void k_edgemax(const float* __restrict__ bedge, float* __restrict__ emb) {
    int warp = (blockIdx.x * blockDim.x + threadIdx.x) >> 5;
    int lane = threadIdx.x & 31;
    if (warp >= NN) return;
    int beg = g_off[warp], end = g_off[warp + 1];
    float4 m = make_float4(-3.402823466e38f, -3.402823466e38f,
                           -3.402823466e38f, -3.402823466e38f);
    for (int e = beg; e < end; e++) {
        int s = g_srcv[e];
        float4 q = *(const float4*)(g_Q + (size_t)s * FD + lane * 4);
        m.x = fmaxf(m.x, q.x); m.y = fmaxf(m.y, q.y);
        m.z = fmaxf(m.z, q.z); m.w = fmaxf(m.w, q.w);
    }
    float4 val;
    if (end > beg) {
        float4 p = *(const float4*)(g_P + (size_t)warp * FD + lane * 4);
        float4 b = *(const float4*)(bedge + lane * 4);
        val.x = p.x + b.x + m.x; val.y = p.y + b.y + m.y;
        val.z = p.z + b.z + m.z; val.w = p.w + b.w + m.w;
    } else {
        val = make_float4(0.f, 0.f, 0.f, 0.f);
    }
    if (emb) *(float4*)(emb + (size_t)warp * FD + lane * 4) = val;
    float4 r;
    r.x = fmaxf(val.x, 0.f); r.y = fmaxf(val.y, 0.f);
    r.z = fmaxf(val.z, 0.f); r.w = fmaxf(val.w, 0.f);
    *(float4*)(g_E + (size_t)warp * FD + lane * 4) = r;
}

// ---------------- graph pooling ----------------
__device__ __forceinline__ int lb_batch(const int* __restrict__ b, int val) {
    int lo = 0, hi = NN;
    while (lo < hi) {
        int mid = (lo + hi) >> 1;
        if (b[mid] < val) lo = mid + 1; else hi = mid;
    }
    return lo;
}

__global__ void k_pool(const int* __restrict__ batch) {
    int g = blockIdx.x;
    int f = threadIdx.x;
    __shared__ int s_lo, s_hi;
    if (f == 0) { s_lo = lb_batch(batch, g); s_hi = lb_batch(batch, g + 1); }
    __syncthreads();
    int lo = s_lo, hi = s_hi;
    float acc = 0.f;
    if (f < FD) {
#pragma unroll 4
        for (int i = lo; i < hi; i++) acc += g_H[(size_t)i * FD + f];
    } else {
        int ff = f - FD;
#pragma unroll 4
        for (int i = lo; i < hi; i++)
            acc += (float)g_degraw[i] * g_E[(size_t)i * FD + ff];
    }
    g_G[g * 2 * FD + f] = acc;
}

// ---------------- readout MLP ----------------
__global__ void k_mlp(const float* __restrict__ W0, const float* __restrict__ b0,
                      const float* __restrict__ W1, const float* __restrict__ b1,
                      float* __restrict__ out) {
    int g = blockIdx.x;
    int j = threadIdx.x;
    __shared__ float sg[2 * FD];
    __shared__ float sh[HIDN];
    sg[j] = g_G[g * 2 * FD + j];
    __syncthreads();
    float a = b0[j];
#pragma unroll 4
    for (int k = 0; k < 2 * FD; k++) a = fmaf(sg[k], W0[k * HIDN + j], a);
    sh[j] = fmaxf(a, 0.f);
    __syncthreads();
    if (j < ODIM) {
        float o = b1[j];
#pragma unroll 4
        for (int k = 0; k < HIDN; k++) o = fmaf(sh[k], W1[k * ODIM + j], o);
        out[g * ODIM + j] = fmaxf(o, 0.f);
    }
}

// ---------------- zero fill for emb_edge rows >= NN ----------------
__global__ void k_zerotail(float* __restrict__ p, long long n4) {
    long long i = (long long)blockIdx.x * blockDim.x + threadIdx.x;
    if (i < n4) ((float4*)p)[i] = make_float4(0.f, 0.f, 0.f, 0.f);
}

// ---------------- launch (fork/join; pq1 placed at submission index 3 for ncu) ----------------
extern "C" void kernel_launch(void* const* d_in, const int* in_sizes, int n_in,
                              void* d_out, int out_size) {
    const float* x     = (const float*)d_in[0];
    const float* ea    = (const float*)d_in[1];
    const int*   ei    = (const int*)d_in[2];
    const int*   batch = (const int*)d_in[3];
    const float* Wlin  = (const float*)d_in[4];
    const float* blin  = (const float*)d_in[5];
    const float* Wroot = (const float*)d_in[6];
    const float* Wedge = (const float*)d_in[7];
    const float* bedge = (const float*)d_in[8];
    const float* W0    = (const float*)d_in[9];
    const float* b0    = (const float*)d_in[10];
    const float* W1    = (const float*)d_in[11];
    const float* b1    = (const float*)d_in[12];

    float* out      = (float*)d_out;
    float* emb_node = out + NG * ODIM;
    float* emb_edge = emb_node + (size_t)NN * FD;

    const int* row = ei;
    const int* col = ei + NE;

    static cudaStream_t sB = nullptr, sC = nullptr;
    static cudaEvent_t evStart, evInit, evCSR, evE2, evCdone;
    if (!sB) {
        cudaStreamCreateWithFlags(&sB, cudaStreamNonBlocking);
        cudaStreamCreateWithFlags(&sC, cudaStreamNonBlocking);
        cudaEventCreateWithFlags(&evStart, cudaEventDisableTiming);
        cudaEventCreateWithFlags(&evInit,  cudaEventDisableTiming);
        cudaEventCreateWithFlags(&evCSR,   cudaEventDisableTiming);
        cudaEventCreateWithFlags(&evE2,    cudaEventDisableTiming);
        cudaEventCreateWithFlags(&evCdone, cudaEventDisableTiming);
    }

    dim3 b256(256);
    int gN = (NN + 255) / 256;
    int gE = (NE + 255) / 256;
    int gW = NN / 8;
    dim3 gMF((NN + 63) / 64, MAXD + 1);
    int gPQ = (NN + 63) / 64;
    long long n4 = (long long)(NE - NN) * FD / 4;

    // ---- fork C: zero tail of emb_edge (submission 0; no dependencies) ----
    cudaEventRecord(evStart, 0);
    cudaStreamWaitEvent(sC, evStart, 0);
    k_zerotail<<<(unsigned)((n4 + 255) / 256), b256, 0, sC>>>(
        emb_edge + (size_t)NN * FD, n4);
    cudaEventRecord(evCdone, sC);

    // ---- main: init(1), count(2) ----
    k_init<<<gN, b256>>>(Wedge);
    k_count<<<gE, b256>>>(col);
    cudaEventRecord(evInit, 0);

    // ---- fork B: pq iter 1 (submission 3 — this is the one ncu profiles) ----
    cudaStreamWaitEvent(sB, evInit, 0);
    k_pq<<<gPQ, b256, 0, sB>>>(ea, 0, Wedge);

    // ---- main: rest of CSR/bucket prep ----
    k_bcount<<<gN, b256>>>();
    k_scan1<<<NSCB, SCB>>>();
    k_scan2<<<1, 1>>>();
    k_scan3<<<NSCB, SCB>>>();
    k_bfill<<<gN, b256>>>();
    k_fillcsr<<<gE, b256>>>(row, col);
    cudaEventRecord(evCSR, 0);

    // ---- stream B: rest of edge path ----
    cudaStreamWaitEvent(sB, evCSR, 0);
    k_edgemax<<<gW, b256, 0, sB>>>(bedge, nullptr);
    k_pq<<<gPQ, b256, 0, sB>>>(nullptr, 1, Wedge);
    k_edgemax<<<gW, b256, 0, sB>>>(bedge, emb_edge);
    cudaEventRecord(evE2, sB);

    // ---- main: node path ----
    k_nsum<<<gW, b256>>>(x, 0);
    k_mf<<<gMF, b256>>>(x, 0, Wlin, blin, Wroot, nullptr);
    k_nsum<<<gW, b256>>>(nullptr, 1);
    k_mf<<<gMF, b256>>>(nullptr, 1, Wlin, blin, Wroot, emb_node);
    k_nsum<<<gW, b256>>>(nullptr, 1);

    // ---- join + readout ----
    cudaStreamWaitEvent(0, evE2, 0);
    k_pool<<<NG, b256>>>(batch);
    k_mlp<<<NG, b256>>>(W0, b0, W1, b1, out);
    cudaStreamWaitEvent(0, evCdone, 0);
}

// round 5
// speedup vs baseline: 1.5144x; 1.0284x over previous
#include <cuda_runtime.h>

#define NN   50000
#define NE   600000
#define FD   128
#define NG   256
#define HIDN 256
#define ODIM 16
#define MAXD 10
#define SCB  512
#define NSCB ((NN + SCB - 1) / SCB)   // 98

typedef unsigned long long u64;

// ---------------- scratch (device globals; no allocs) ----------------
__device__ int   g_degraw[NN];
__device__ int   g_off[NN + 1];
__device__ int   g_cursor[NN];
__device__ int   g_srcv[NE];
__device__ int   g_bcnt[MAXD + 1];
__device__ int   g_boff[MAXD + 2];
__device__ int   g_bcur[MAXD + 1];
__device__ int   g_bnodes[NN];
__device__ int   g_bsum[NSCB];
__device__ float g_X[NN * FD];
__device__ float g_H[NN * FD];
__device__ float g_E[NN * FD];
__device__ float g_P[NN * FD];
__device__ float g_Q[NN * FD];
__device__ float g_Wd[FD * FD];
__device__ float g_G[NG * 2 * FD];

// ---------------- helpers ----------------
__device__ __forceinline__ u64 pk2(float a, float b) {
    u64 r; asm("mov.b64 %0, {%1,%2};" : "=l"(r) : "f"(a), "f"(b)); return r;
}
__device__ __forceinline__ u64 fma2(u64 a, u64 b, u64 c) {
    u64 d; asm("fma.rn.f32x2 %0, %1, %2, %3;" : "=l"(d) : "l"(a), "l"(b), "l"(c)); return d;
}
__device__ __forceinline__ float2 upk(u64 v) {
    float2 f; asm("mov.b64 {%0,%1}, %2;" : "=f"(f.x), "=f"(f.y) : "l"(v)); return f;
}
__device__ __forceinline__ void cpa16(float* s, const float4* g) {
    unsigned a = (unsigned)__cvta_generic_to_shared(s);
    asm volatile("cp.async.cg.shared.global [%0], [%1], 16;" :: "r"(a), "l"(g) : "memory");
}
__device__ __forceinline__ void cpa_commit() {
    asm volatile("cp.async.commit_group;" ::: "memory");
}
__device__ __forceinline__ void cpa_wait0() {
    asm volatile("cp.async.wait_group 0;" ::: "memory");
}

// ---------------- prep ----------------
__global__ void k_init(const float* __restrict__ Wedge) {
    int i = blockIdx.x * blockDim.x + threadIdx.x;
    if (i < NN) { g_degraw[i] = 0; g_cursor[i] = 0; }
    if (i <= MAXD) { g_bcnt[i] = 0; g_bcur[i] = 0; }
    if (i < FD * FD) g_Wd[i] = Wedge[i] - Wedge[FD * FD + i];
}

__global__ void k_count(const int* __restrict__ col) {
    int e = blockIdx.x * blockDim.x + threadIdx.x;
    if (e < NE) atomicAdd(&g_degraw[col[e]], 1);
}

__global__ void k_bcount() {
    __shared__ int h[MAXD + 1];
    int tid = threadIdx.x;
    if (tid <= MAXD) h[tid] = 0;
    __syncthreads();
    int i = blockIdx.x * blockDim.x + tid;
    if (i < NN) atomicAdd(&h[min(g_degraw[i], MAXD)], 1);
    __syncthreads();
    if (tid <= MAXD && h[tid]) atomicAdd(&g_bcnt[tid], h[tid]);
}

__global__ void k_scan1() {
    __shared__ int sd[SCB];
    int tid = threadIdx.x;
    int i = blockIdx.x * SCB + tid;
    sd[tid] = (i < NN) ? g_degraw[i] : 0;
    __syncthreads();
    for (int off = SCB / 2; off > 0; off >>= 1) {
        if (tid < off) sd[tid] += sd[tid + off];
        __syncthreads();
    }
    if (tid == 0) g_bsum[blockIdx.x] = sd[0];
}

__global__ void k_scan2() {
    int s = 0;
    for (int b = 0; b < NSCB; b++) { int v = g_bsum[b]; g_bsum[b] = s; s += v; }
    g_off[NN] = s;
    int t = 0;
    for (int d = 0; d <= MAXD; d++) { g_boff[d] = t; t += g_bcnt[d]; }
    g_boff[MAXD + 1] = t;
}

__global__ void k_scan3() {
    __shared__ int sd[SCB];
    int tid = threadIdx.x;
    int i = blockIdx.x * SCB + tid;
    int v = (i < NN) ? g_degraw[i] : 0;
    sd[tid] = v;
    __syncthreads();
    for (int off = 1; off < SCB; off <<= 1) {
        int t = 0;
        if (tid >= off) t = sd[tid - off];
        __syncthreads();
        if (tid >= off) sd[tid] += t;
        __syncthreads();
    }
    if (i < NN) g_off[i] = g_bsum[blockIdx.x] + sd[tid] - v;
}

__global__ void k_bfill() {
    __shared__ int h[MAXD + 1];
    __shared__ int sbase[MAXD + 1];
    int tid = threadIdx.x;
    if (tid <= MAXD) h[tid] = 0;
    __syncthreads();
    int i = blockIdx.x * blockDim.x + tid;
    int d = -1;
    if (i < NN) { d = min(g_degraw[i], MAXD); atomicAdd(&h[d], 1); }
    __syncthreads();
    if (tid <= MAXD) {
        sbase[tid] = h[tid] ? atomicAdd(&g_bcur[tid], h[tid]) : 0;
        h[tid] = 0;
    }
    __syncthreads();
    if (i < NN) {
        int p = atomicAdd(&h[d], 1);
        g_bnodes[g_boff[d] + sbase[d] + p] = i;
    }
}

__global__ void k_fillcsr(const int* __restrict__ row, const int* __restrict__ col) {
    int e = blockIdx.x * blockDim.x + threadIdx.x;
    if (e < NE) {
        int c = col[e];
        int p = atomicAdd(&g_cursor[c], 1);
        g_srcv[g_off[c] + p] = row[e];
    }
}

// ---------------- neighbor sum ----------------
__global__ void k_nsum(const float* __restrict__ Xext, int use_internal) {
    const float* __restrict__ X = use_internal ? g_X : Xext;
    int warp = (blockIdx.x * blockDim.x + threadIdx.x) >> 5;
    int lane = threadIdx.x & 31;
    if (warp >= NN) return;
    int beg = g_off[warp], end = g_off[warp + 1];
    float4 acc = make_float4(0.f, 0.f, 0.f, 0.f);
    for (int e = beg; e < end; e++) {
        int s = g_srcv[e];
        float4 v = *(const float4*)(X + (size_t)s * FD + lane * 4);
        acc.x += v.x; acc.y += v.y; acc.z += v.z; acc.w += v.w;
    }
    *(float4*)(g_H + (size_t)warp * FD + lane * 4) = acc;
}

// ---------------- MFConv bucketed dual-GEMM (f32x2, pipelined) ----------------
// dynamic smem layout (floats): sWl[2][2048] | sWr[2][2048] | sAh[2][1024] | sAx[2][1024]
__global__ void __launch_bounds__(256, 2) k_mf(
        const float* __restrict__ Xext, int use_internal,
        const float* __restrict__ Wlin, const float* __restrict__ blin,
        const float* __restrict__ Wroot, float* __restrict__ emb) {
    const float* __restrict__ Xin = use_internal ? g_X : Xext;
    int d = blockIdx.y;
    int bstart = g_boff[d];
    int bcnt = g_boff[d + 1] - bstart;
    int base = blockIdx.x * 64;
    if (base >= bcnt) return;
    int nv = min(64, bcnt - base);

    extern __shared__ float smd[];
    float* sWl = smd;                  // 2 * 2048
    float* sWr = smd + 4096;           // 2 * 2048
    float* sAh = smd + 8192;           // 2 * 1024
    float* sAx = smd + 10240;          // 2 * 1024
    __shared__ int s_node[64];

    int tid = threadIdx.x;
    if (tid < 64) s_node[tid] = (tid < nv) ? g_bnodes[bstart + base + tid] : -1;
    __syncthreads();

    const float* Wl = Wlin + (size_t)d * FD * FD;
    const float* Wr = Wroot + (size_t)d * FD * FD;

    int nA = tid >> 2;          // staging node slot 0..63
    int kq = tid & 3;           // staging k-quad 0..3
    int nodeA = s_node[nA];
    const float* pH = g_H + (nodeA >= 0 ? (size_t)nodeA * FD : 0) + kq * 4;
    const float* pX = Xin + (nodeA >= 0 ? (size_t)nodeA * FD : 0) + kq * 4;

    u64 acc[4][4];
#pragma unroll
    for (int a = 0; a < 4; a++)
#pragma unroll
        for (int b = 0; b < 4; b++) acc[a][b] = 0ull;

    int o0 = (tid & 31) * 4;
    int n0 = (tid >> 5) * 8;

    // ---- stage chunk 0 ----
    {
        const float4* Wl4 = (const float4*)Wl;
        const float4* Wr4 = (const float4*)Wr;
        cpa16(&sWl[4 * tid], Wl4 + tid);
        cpa16(&sWl[4 * (tid + 256)], Wl4 + tid + 256);
        cpa16(&sWr[4 * tid], Wr4 + tid);
        cpa16(&sWr[4 * (tid + 256)], Wr4 + tid + 256);
        cpa_commit();
        float4 vh = make_float4(0.f, 0.f, 0.f, 0.f), vx = vh;
        if (nodeA >= 0) { vh = *(const float4*)pH; vx = *(const float4*)pX; }
        sAh[(kq * 4 + 0) * 64 + nA] = vh.x; sAh[(kq * 4 + 1) * 64 + nA] = vh.y;
        sAh[(kq * 4 + 2) * 64 + nA] = vh.z; sAh[(kq * 4 + 3) * 64 + nA] = vh.w;
        sAx[(kq * 4 + 0) * 64 + nA] = vx.x; sAx[(kq * 4 + 1) * 64 + nA] = vx.y;
        sAx[(kq * 4 + 2) * 64 + nA] = vx.z; sAx[(kq * 4 + 3) * 64 + nA] = vx.w;
        cpa_wait0();
    }
    __syncthreads();

#pragma unroll
    for (int c = 0; c < 8; c++) {
        int cur = c & 1, nxt = cur ^ 1;
        float4 vh, vx;
        if (c < 7) {
            int k0n = (c + 1) * 16;
            const float4* Wl4 = (const float4*)(Wl + (size_t)k0n * FD);
            const float4* Wr4 = (const float4*)(Wr + (size_t)k0n * FD);
            cpa16(&sWl[nxt * 2048 + 4 * tid], Wl4 + tid);
            cpa16(&sWl[nxt * 2048 + 4 * (tid + 256)], Wl4 + tid + 256);
            cpa16(&sWr[nxt * 2048 + 4 * tid], Wr4 + tid);
            cpa16(&sWr[nxt * 2048 + 4 * (tid + 256)], Wr4 + tid + 256);
            cpa_commit();
            vh = make_float4(0.f, 0.f, 0.f, 0.f); vx = vh;
            if (nodeA >= 0) {
                vh = *(const float4*)(pH + k0n);
                vx = *(const float4*)(pX + k0n);
            }
        }
        const float* wlb = &sWl[cur * 2048];
        const float* wrb = &sWr[cur * 2048];
        const float* ahb = &sAh[cur * 1024];
        const float* axb = &sAx[cur * 1024];
#pragma unroll
        for (int kk = 0; kk < 16; kk++) {
            float4 wl = *(const float4*)&wlb[kk * 128 + o0];
            float4 wr = *(const float4*)&wrb[kk * 128 + o0];
            u64 wl2[4] = {pk2(wl.x, wl.x), pk2(wl.y, wl.y), pk2(wl.z, wl.z), pk2(wl.w, wl.w)};
            u64 wr2[4] = {pk2(wr.x, wr.x), pk2(wr.y, wr.y), pk2(wr.z, wr.z), pk2(wr.w, wr.w)};
            const u64* ah2 = (const u64*)&ahb[kk * 64 + n0];
            const u64* ax2 = (const u64*)&axb[kk * 64 + n0];
#pragma unroll
            for (int a = 0; a < 4; a++) {
                u64 ahv = ah2[a], axv = ax2[a];
#pragma unroll
                for (int b = 0; b < 4; b++) {
                    acc[a][b] = fma2(ahv, wl2[b], acc[a][b]);
                    acc[a][b] = fma2(axv, wr2[b], acc[a][b]);
                }
            }
        }
        if (c < 7) {
            sAh[nxt * 1024 + (kq * 4 + 0) * 64 + nA] = vh.x;
            sAh[nxt * 1024 + (kq * 4 + 1) * 64 + nA] = vh.y;
            sAh[nxt * 1024 + (kq * 4 + 2) * 64 + nA] = vh.z;
            sAh[nxt * 1024 + (kq * 4 + 3) * 64 + nA] = vh.w;
            sAx[nxt * 1024 + (kq * 4 + 0) * 64 + nA] = vx.x;
            sAx[nxt * 1024 + (kq * 4 + 1) * 64 + nA] = vx.y;
            sAx[nxt * 1024 + (kq * 4 + 2) * 64 + nA] = vx.z;
            sAx[nxt * 1024 + (kq * 4 + 3) * 64 + nA] = vx.w;
            cpa_wait0();
            __syncthreads();
        }
    }

    float4 bl = *(const float4*)(blin + (size_t)d * FD + o0);
    float bv[4] = {bl.x, bl.y, bl.z, bl.w};
#pragma unroll
    for (int a = 0; a < 4; a++) {
        float2 c0 = upk(acc[a][0]), c1 = upk(acc[a][1]);
        float2 c2 = upk(acc[a][2]), c3 = upk(acc[a][3]);
#pragma unroll
        for (int half = 0; half < 2; half++) {
            int node = s_node[n0 + 2 * a + half];
            if (node < 0) continue;
            float4 v;
            v.x = (half ? c0.y : c0.x) + bv[0];
            v.y = (half ? c1.y : c1.x) + bv[1];
            v.z = (half ? c2.y : c2.x) + bv[2];
            v.w = (half ? c3.y : c3.x) + bv[3];
            if (emb) *(float4*)(emb + (size_t)node * FD + o0) = v;
            float4 r;
            r.x = fmaxf(v.x, 0.f); r.y = fmaxf(v.y, 0.f);
            r.z = fmaxf(v.z, 0.f); r.w = fmaxf(v.w, 0.f);
            *(float4*)(g_X + (size_t)node * FD + o0) = r;
        }
    }
}

// ---------------- EdgeConv projections (f32x2, pipelined) ----------------
__global__ void __launch_bounds__(256, 2) k_pq(
        const float* __restrict__ Eext, int use_internal,
        const float* __restrict__ Wedge) {
    const float* __restrict__ Ein = use_internal ? g_E : Eext;
    const float* __restrict__ Wb = Wedge + FD * FD;
    int base = blockIdx.x * 64;

    __shared__ float sWd[2][2048];
    __shared__ float sWb[2][2048];
    __shared__ float sAe[2][1024];

    int tid = threadIdx.x;
    int nA = tid >> 2;
    int kq = tid & 3;
    int nodeA = base + nA;
    const float* pE = Ein + (nodeA < NN ? (size_t)nodeA * FD : 0) + kq * 4;

    u64 accP[4][4], accQ[4][4];
#pragma unroll
    for (int a = 0; a < 4; a++)
#pragma unroll
        for (int b = 0; b < 4; b++) { accP[a][b] = 0ull; accQ[a][b] = 0ull; }

    int o0 = (tid & 31) * 4;
    int n0 = (tid >> 5) * 8;

    // ---- stage chunk 0 ----
    {
        const float4* Wd4 = (const float4*)g_Wd;
        const float4* Wb4 = (const float4*)Wb;
        cpa16(&sWd[0][4 * tid], Wd4 + tid);
        cpa16(&sWd[0][4 * (tid + 256)], Wd4 + tid + 256);
        cpa16(&sWb[0][4 * tid], Wb4 + tid);
        cpa16(&sWb[0][4 * (tid + 256)], Wb4 + tid + 256);
        cpa_commit();
        float4 v = make_float4(0.f, 0.f, 0.f, 0.f);
        if (nodeA < NN) v = *(const float4*)pE;
        sAe[0][(kq * 4 + 0) * 64 + nA] = v.x; sAe[0][(kq * 4 + 1) * 64 + nA] = v.y;
        sAe[0][(kq * 4 + 2) * 64 + nA] = v.z; sAe[0][(kq * 4 + 3) * 64 + nA] = v.w;
        cpa_wait0();
    }
    __syncthreads();

#pragma unroll
    for (int c = 0; c < 8; c++) {
        int cur = c & 1, nxt = cur ^ 1;
        float4 v;
        if (c < 7) {
            int k0n = (c + 1) * 16;
            const float4* Wd4 = (const float4*)(g_Wd + (size_t)k0n * FD);
            const float4* Wb4 = (const float4*)(Wb + (size_t)k0n * FD);
            cpa16(&sWd[nxt][4 * tid], Wd4 + tid);
            cpa16(&sWd[nxt][4 * (tid + 256)], Wd4 + tid + 256);
            cpa16(&sWb[nxt][4 * tid], Wb4 + tid);
            cpa16(&sWb[nxt][4 * (tid + 256)], Wb4 + tid + 256);
            cpa_commit();
            v = make_float4(0.f, 0.f, 0.f, 0.f);
            if (nodeA < NN) v = *(const float4*)(pE + k0n);
        }
#pragma unroll
        for (int kk = 0; kk < 16; kk++) {
            float4 wd = *(const float4*)&sWd[cur][kk * 128 + o0];
            float4 wb = *(const float4*)&sWb[cur][kk * 128 + o0];
            u64 wd2[4] = {pk2(wd.x, wd.x), pk2(wd.y, wd.y), pk2(wd.z, wd.z), pk2(wd.w, wd.w)};
            u64 wb2[4] = {pk2(wb.x, wb.x), pk2(wb.y, wb.y), pk2(wb.z, wb.z), pk2(wb.w, wb.w)};
            const u64* ae2 = (const u64*)&sAe[cur][kk * 64 + n0];
#pragma unroll
            for (int a = 0; a < 4; a++) {
                u64 av = ae2[a];
#pragma unroll
                for (int b = 0; b < 4; b++) {
                    accP[a][b] = fma2(av, wd2[b], accP[a][b]);
                    accQ[a][b] = fma2(av, wb2[b], accQ[a][b]);
                }
            }
        }
        if (c < 7) {
            sAe[nxt][(kq * 4 + 0) * 64 + nA] = v.x;
            sAe[nxt][(kq * 4 + 1) * 64 + nA] = v.y;
            sAe[nxt][(kq * 4 + 2) * 64 + nA] = v.z;
            sAe[nxt][(kq * 4 + 3) * 64 + nA] = v.w;
            cpa_wait0();
            __syncthreads();
        }
    }

#pragma unroll
    for (int a = 0; a < 4; a++) {
        float2 p0 = upk(accP[a][0]), p1 = upk(accP[a][1]);
        float2 p2 = upk(accP[a][2]), p3 = upk(accP[a][3]);
        float2 q0 = upk(accQ[a][0]), q1 = upk(accQ[a][1]);
        float2 q2 = upk(accQ[a][2]), q3 = upk(accQ[a][3]);
#pragma unroll
        for (int half = 0; half < 2; half++) {
            int node = base + n0 + 2 * a + half;
            if (node >= NN) continue;
            float4 p, q;
            p.x = half ? p0.y : p0.x; p.y = half ? p1.y : p1.x;
            p.z = half ? p2.y : p2.x; p.w = half ? p3.y : p3.x;
            q.x = half ? q0.y : q0.x; q.y = half ? q1.y : q1.x;
            q.z = half ? q2.y : q2.x; q.w = half ? q3.y : q3.x;
            *(float4*)(g_P + (size_t)node * FD + o0) = p;
            *(float4*)(g_Q + (size_t)node * FD + o0) = q;
        }
    }
}

// ---------------- Edge max aggregation ----------------
__global__ void k_edgemax(const float* __restrict__ bedge, float* __restrict__ emb) {
    int warp = (blockIdx.x * blockDim.x + threadIdx.x) >> 5;
    int lane = threadIdx.x & 31;
    if (warp >= NN) return;
    int beg = g_off[warp], end = g_off[warp + 1];
    float4 m = make_float4(-3.402823466e38f, -3.402823466e38f,
                           -3.402823466e38f, -3.402823466e38f);
    for (int e = beg; e < end; e++) {
        int s = g_srcv[e];
        float4 q = *(const float4*)(g_Q + (size_t)s * FD + lane * 4);
        m.x = fmaxf(m.x, q.x); m.y = fmaxf(m.y, q.y);
        m.z = fmaxf(m.z, q.z); m.w = fmaxf(m.w, q.w);
    }
    float4 val;
    if (end > beg) {
        float4 p = *(const float4*)(g_P + (size_t)warp * FD + lane * 4);
        float4 b = *(const float4*)(bedge + lane * 4);
        val.x = p.x + b.x + m.x; val.y = p.y + b.y + m.y;
        val.z = p.z + b.z + m.z; val.w = p.w + b.w + m.w;
    } else {
        val = make_float4(0.f, 0.f, 0.f, 0.f);
    }
    if (emb) *(float4*)(emb + (size_t)warp * FD + lane * 4) = val;
    float4 r;
    r.x = fmaxf(val.x, 0.f); r.y = fmaxf(val.y, 0.f);
    r.z = fmaxf(val.z, 0.f); r.w = fmaxf(val.w, 0.f);
    *(float4*)(g_E + (size_t)warp * FD + lane * 4) = r;
}

// ---------------- graph pooling ----------------
__device__ __forceinline__ int lb_batch(const int* __restrict__ b, int val) {
    int lo = 0, hi = NN;
    while (lo < hi) {
        int mid = (lo + hi) >> 1;
        if (b[mid] < val) lo = mid + 1; else hi = mid;
    }
    return lo;
}

__global__ void k_pool(const int* __restrict__ batch) {
    int g = blockIdx.x;
    int f = threadIdx.x;
    __shared__ int s_lo, s_hi;
    if (f == 0) { s_lo = lb_batch(batch, g); s_hi = lb_batch(batch, g + 1); }
    __syncthreads();
    int lo = s_lo, hi = s_hi;
    float acc = 0.f;
    if (f < FD) {
#pragma unroll 4
        for (int i = lo; i < hi; i++) acc += g_H[(size_t)i * FD + f];
    } else {
        int ff = f - FD;
#pragma unroll 4
        for (int i = lo; i < hi; i++)
            acc += (float)g_degraw[i] * g_E[(size_t)i * FD + ff];
    }
    g_G[g * 2 * FD + f] = acc;
}

// ---------------- readout MLP ----------------
__global__ void k_mlp(const float* __restrict__ W0, const float* __restrict__ b0,
                      const float* __restrict__ W1, const float* __restrict__ b1,
                      float* __restrict__ out) {
    int g = blockIdx.x;
    int j = threadIdx.x;
    __shared__ float sg[2 * FD];
    __shared__ float sh[HIDN];
    sg[j] = g_G[g * 2 * FD + j];
    __syncthreads();
    float a = b0[j];
#pragma unroll 4
    for (int k = 0; k < 2 * FD; k++) a = fmaf(sg[k], W0[k * HIDN + j], a);
    sh[j] = fmaxf(a, 0.f);
    __syncthreads();
    if (j < ODIM) {
        float o = b1[j];
#pragma unroll 4
        for (int k = 0; k < HIDN; k++) o = fmaf(sh[k], W1[k * ODIM + j], o);
        out[g * ODIM + j] = fmaxf(o, 0.f);
    }
}

// ---------------- zero fill for emb_edge rows >= NN ----------------
__global__ void k_zerotail(float* __restrict__ p, long long n4) {
    long long i = (long long)blockIdx.x * blockDim.x + threadIdx.x;
    if (i < n4) ((float4*)p)[i] = make_float4(0.f, 0.f, 0.f, 0.f);
}

// ---------------- launch (fork/join; pq1 at submission index 3 for ncu) ----------------
extern "C" void kernel_launch(void* const* d_in, const int* in_sizes, int n_in,
                              void* d_out, int out_size) {
    const float* x     = (const float*)d_in[0];
    const float* ea    = (const float*)d_in[1];
    const int*   ei    = (const int*)d_in[2];
    const int*   batch = (const int*)d_in[3];
    const float* Wlin  = (const float*)d_in[4];
    const float* blin  = (const float*)d_in[5];
    const float* Wroot = (const float*)d_in[6];
    const float* Wedge = (const float*)d_in[7];
    const float* bedge = (const float*)d_in[8];
    const float* W0    = (const float*)d_in[9];
    const float* b0    = (const float*)d_in[10];
    const float* W1    = (const float*)d_in[11];
    const float* b1    = (const float*)d_in[12];

    float* out      = (float*)d_out;
    float* emb_node = out + NG * ODIM;
    float* emb_edge = emb_node + (size_t)NN * FD;

    const int* row = ei;
    const int* col = ei + NE;

    const int MF_SMEM = 12288 * 4;   // 48 KB dynamic

    static cudaStream_t sB = nullptr, sC = nullptr;
    static cudaEvent_t evStart, evInit, evCSR, evE2, evCdone;
    if (!sB) {
        cudaStreamCreateWithFlags(&sB, cudaStreamNonBlocking);
        cudaStreamCreateWithFlags(&sC, cudaStreamNonBlocking);
        cudaEventCreateWithFlags(&evStart, cudaEventDisableTiming);
        cudaEventCreateWithFlags(&evInit,  cudaEventDisableTiming);
        cudaEventCreateWithFlags(&evCSR,   cudaEventDisableTiming);
        cudaEventCreateWithFlags(&evE2,    cudaEventDisableTiming);
        cudaEventCreateWithFlags(&evCdone, cudaEventDisableTiming);
        cudaFuncSetAttribute(k_mf, cudaFuncAttributeMaxDynamicSharedMemorySize, MF_SMEM);
    }

    dim3 b256(256);
    int gN = (NN + 255) / 256;
    int gE = (NE + 255) / 256;
    int gW = NN / 8;
    dim3 gMF((NN + 63) / 64, MAXD + 1);
    int gPQ = (NN + 63) / 64;
    long long n4 = (long long)(NE - NN) * FD / 4;

    // ---- fork C: zero tail of emb_edge (submission 0; no dependencies) ----
    cudaEventRecord(evStart, 0);
    cudaStreamWaitEvent(sC, evStart, 0);
    k_zerotail<<<(unsigned)((n4 + 255) / 256), b256, 0, sC>>>(
        emb_edge + (size_t)NN * FD, n4);
    cudaEventRecord(evCdone, sC);

    // ---- main: init(1), count(2) ----
    k_init<<<gN, b256>>>(Wedge);
    k_count<<<gE, b256>>>(col);
    cudaEventRecord(evInit, 0);

    // ---- fork B: pq iter 1 (submission 3 — profiled by ncu) ----
    cudaStreamWaitEvent(sB, evInit, 0);
    k_pq<<<gPQ, b256, 0, sB>>>(ea, 0, Wedge);

    // ---- main: rest of CSR/bucket prep ----
    k_bcount<<<gN, b256>>>();
    k_scan1<<<NSCB, SCB>>>();
    k_scan2<<<1, 1>>>();
    k_scan3<<<NSCB, SCB>>>();
    k_bfill<<<gN, b256>>>();
    k_fillcsr<<<gE, b256>>>(row, col);
    cudaEventRecord(evCSR, 0);

    // ---- stream B: rest of edge path ----
    cudaStreamWaitEvent(sB, evCSR, 0);
    k_edgemax<<<gW, b256, 0, sB>>>(bedge, nullptr);
    k_pq<<<gPQ, b256, 0, sB>>>(nullptr, 1, Wedge);
    k_edgemax<<<gW, b256, 0, sB>>>(bedge, emb_edge);
    cudaEventRecord(evE2, sB);

    // ---- main: node path ----
    k_nsum<<<gW, b256>>>(x, 0);
    k_mf<<<gMF, b256, MF_SMEM>>>(x, 0, Wlin, blin, Wroot, nullptr);
    k_nsum<<<gW, b256>>>(nullptr, 1);
    k_mf<<<gMF, b256, MF_SMEM>>>(nullptr, 1, Wlin, blin, Wroot, emb_node);
    k_nsum<<<gW, b256>>>(nullptr, 1);

    // ---- join + readout ----
    cudaStreamWaitEvent(0, evE2, 0);
    k_pool<<<NG, b256>>>(batch);
    k_mlp<<<NG, b256>>>(W0, b0, W1, b1, out);
    cudaStreamWaitEvent(0, evCdone, 0);
}